// round 1
// baseline (speedup 1.0000x reference)
#include <cuda_runtime.h>
#include <math.h>

#define BDIM   4
#define TXQ    4096
#define TXFK   256
#define DMODEL 1024
#define DTEXT  768
#define NHEADS 16
#define HDIM   64
#define MQ     (BDIM*TXQ)     // 16384
#define MKV    (BDIM*TXFK)    // 1024
#define DFF    4096
#define ATT_SCALE 0.125f      // 64^-0.5

// ---------------- scratch (device globals; no allocation allowed) -------------
__device__ float g_q   [(size_t)MQ  * DMODEL];   // 64 MB
__device__ float g_k   [(size_t)MKV * DMODEL];   // 4 MB
__device__ float g_v   [(size_t)MKV * DMODEL];   // 4 MB
__device__ float g_attn[(size_t)MQ  * DMODEL];   // 64 MB
__device__ float g_res [(size_t)MQ  * DMODEL];   // out = attn@Wo+bo (residual base)
__device__ float g_ln  [(size_t)MQ  * DMODEL];   // LayerNorm(out)
__device__ float g_h   [(size_t)MQ  * DFF];      // GELU(ln@W1+b1), 256 MB

__device__ __forceinline__ float gelu_exact(float v) {
    return 0.5f * v * (1.0f + erff(v * 0.7071067811865476f));
}

// ---------------- generic fp32 SGEMM: C = act(A@W + bias) [+ res1 + res2] ----
// A: [M,K] row-major, W: [K,N] row-major, C: [M,N] row-major.
// BM=BN=128, BK=16, 256 threads, 8x8 per thread. All shapes divisible.
template<int ACT, int NRES>
__global__ void __launch_bounds__(256, 2) sgemm_kernel(
    int M, int N, int K,
    const float* __restrict__ A, const float* __restrict__ W,
    const float* __restrict__ bias,
    const float* __restrict__ res1, const float* __restrict__ res2,
    float* __restrict__ C)
{
    const int BM = 128, BN = 128, BK = 16;
    __shared__ float As[BK][BM];
    __shared__ float Bs[BK][BN];

    const int tid = threadIdx.x;
    const int tx  = tid & 15;        // 0..15 -> col block
    const int ty  = tid >> 4;        // 0..15 -> row block
    const int bx  = blockIdx.x;      // N tile
    const int by  = blockIdx.y;      // M tile

    // A load mapping: 128 rows x 16 cols -> 512 float4; 2 per thread
    const int a_row  = tid >> 2;          // 0..63 (also +64)
    const int a_col4 = (tid & 3) * 4;     // 0,4,8,12
    // W load mapping: 16 rows x 128 cols -> 512 float4; 2 per thread
    const int b_row  = tid >> 5;          // 0..7 (also +8)
    const int b_col4 = (tid & 31) * 4;    // 0..124

    const float* Ab = A + (size_t)by * BM * K;
    const float* Wb = W + (size_t)bx * BN;

    float acc[8][8];
#pragma unroll
    for (int i = 0; i < 8; i++)
#pragma unroll
        for (int j = 0; j < 8; j++) acc[i][j] = 0.0f;

    for (int k0 = 0; k0 < K; k0 += BK) {
        float4 a0 = *(const float4*)(Ab + (size_t)a_row        * K + k0 + a_col4);
        float4 a1 = *(const float4*)(Ab + (size_t)(a_row + 64) * K + k0 + a_col4);
        float4 w0 = *(const float4*)(Wb + (size_t)(k0 + b_row    ) * N + b_col4);
        float4 w1 = *(const float4*)(Wb + (size_t)(k0 + b_row + 8) * N + b_col4);

        As[a_col4 + 0][a_row     ] = a0.x;
        As[a_col4 + 1][a_row     ] = a0.y;
        As[a_col4 + 2][a_row     ] = a0.z;
        As[a_col4 + 3][a_row     ] = a0.w;
        As[a_col4 + 0][a_row + 64] = a1.x;
        As[a_col4 + 1][a_row + 64] = a1.y;
        As[a_col4 + 2][a_row + 64] = a1.z;
        As[a_col4 + 3][a_row + 64] = a1.w;
        *(float4*)&Bs[b_row    ][b_col4] = w0;
        *(float4*)&Bs[b_row + 8][b_col4] = w1;
        __syncthreads();

#pragma unroll
        for (int kk = 0; kk < BK; kk++) {
            float ra[8], rb[8];
            *(float4*)(ra    ) = *(const float4*)&As[kk][ty * 8    ];
            *(float4*)(ra + 4) = *(const float4*)&As[kk][ty * 8 + 4];
            *(float4*)(rb    ) = *(const float4*)&Bs[kk][tx * 8    ];
            *(float4*)(rb + 4) = *(const float4*)&Bs[kk][tx * 8 + 4];
#pragma unroll
            for (int i = 0; i < 8; i++)
#pragma unroll
                for (int j = 0; j < 8; j++)
                    acc[i][j] += ra[i] * rb[j];
        }
        __syncthreads();
    }

    const int row0 = by * BM + ty * 8;
    const int col0 = bx * BN + tx * 8;
#pragma unroll
    for (int i = 0; i < 8; i++) {
        size_t base = (size_t)(row0 + i) * N + col0;
        float4 o[2];
#pragma unroll
        for (int jj = 0; jj < 2; jj++) {
            float vv[4];
#pragma unroll
            for (int j = 0; j < 4; j++) {
                int jc = jj * 4 + j;
                float v = acc[i][jc] + bias[col0 + jc];
                if (ACT == 1) v = gelu_exact(v);
                if (NRES >= 1) v += res1[base + jc];
                if (NRES >= 2) v += res2[base + jc];
                vv[j] = v;
            }
            o[jj] = make_float4(vv[0], vv[1], vv[2], vv[3]);
        }
        *(float4*)(C + base)     = o[0];
        *(float4*)(C + base + 4) = o[1];
    }
}

// ---------------- attention: per (b, h, q-chunk) block ------------------------
// Q: [MQ, DMODEL] (head h occupies cols h*64..), K/V: [MKV, DMODEL].
// Whole 256x64 K and V head-tiles live in padded smem; softmax over all 256 keys.
#define QPB 256
#define KPAD 65

__global__ void __launch_bounds__(256) attn_kernel(
    const float* __restrict__ Q, const float* __restrict__ K,
    const float* __restrict__ V, float* __restrict__ O)
{
    extern __shared__ float sm[];
    float* Ks = sm;                  // 256*65
    float* Vs = Ks + 256 * KPAD;     // 256*65
    float* qs = Vs + 256 * KPAD;     // 8*64
    float* ps = qs + 8 * 64;         // 8*256

    const int nchunk = TXQ / QPB;    // 16
    const int bid   = blockIdx.x;
    const int chunk = bid % nchunk;
    const int h     = (bid / nchunk) % NHEADS;
    const int b     = bid / (nchunk * NHEADS);

    const int tid  = threadIdx.x;
    const int lane = tid & 31;
    const int w    = tid >> 5;

    // load K,V head tiles (256 rows x 64 cols) into padded smem
    for (int i = tid; i < 256 * 16; i += 256) {
        int j  = i >> 4;
        int dq = (i & 15) * 4;
        size_t gbase = (size_t)(b * TXFK + j) * DMODEL + h * HDIM + dq;
        float4 kv = *(const float4*)(K + gbase);
        float4 vv = *(const float4*)(V + gbase);
        Ks[j * KPAD + dq + 0] = kv.x; Ks[j * KPAD + dq + 1] = kv.y;
        Ks[j * KPAD + dq + 2] = kv.z; Ks[j * KPAD + dq + 3] = kv.w;
        Vs[j * KPAD + dq + 0] = vv.x; Vs[j * KPAD + dq + 1] = vv.y;
        Vs[j * KPAD + dq + 2] = vv.z; Vs[j * KPAD + dq + 3] = vv.w;
    }
    __syncthreads();

    for (int qi = 0; qi < 32; qi++) {
        const int qlocal = w * 32 + qi;
        const size_t qrow = (size_t)b * TXQ + (size_t)chunk * QPB + qlocal;
        const float* qp = Q + qrow * DMODEL + h * HDIM;
        qs[w * 64 + lane]      = qp[lane];
        qs[w * 64 + lane + 32] = qp[lane + 32];
        __syncwarp();

        // scores: lane owns keys j = lane + 32*c (conflict-free via KPAD=65)
        float s[8];
#pragma unroll
        for (int c = 0; c < 8; c++) s[c] = 0.0f;
        for (int d = 0; d < 64; d++) {
            float qd = qs[w * 64 + d];
#pragma unroll
            for (int c = 0; c < 8; c++)
                s[c] += qd * Ks[(lane + 32 * c) * KPAD + d];
        }
#pragma unroll
        for (int c = 0; c < 8; c++) s[c] *= ATT_SCALE;

        float mx = s[0];
#pragma unroll
        for (int c = 1; c < 8; c++) mx = fmaxf(mx, s[c]);
#pragma unroll
        for (int o = 16; o; o >>= 1) mx = fmaxf(mx, __shfl_xor_sync(~0u, mx, o));

        float sum = 0.0f;
#pragma unroll
        for (int c = 0; c < 8; c++) { s[c] = __expf(s[c] - mx); sum += s[c]; }
#pragma unroll
        for (int o = 16; o; o >>= 1) sum += __shfl_xor_sync(~0u, sum, o);
        float inv = 1.0f / sum;

#pragma unroll
        for (int c = 0; c < 8; c++) ps[w * 256 + lane + 32 * c] = s[c] * inv;
        __syncwarp();

        // output: lane owns dims d=lane and d=lane+32
        float o0 = 0.0f, o1 = 0.0f;
        for (int j = 0; j < 256; j++) {
            float p = ps[w * 256 + j];
            o0 += p * Vs[j * KPAD + lane];
            o1 += p * Vs[j * KPAD + lane + 32];
        }
        float* op = O + qrow * DMODEL + h * HDIM;
        op[lane]      = o0;
        op[lane + 32] = o1;
        __syncwarp();   // protect qs/ps reuse next iteration
    }
}

// ---------------- LayerNorm over rows of [MQ, 1024] ---------------------------
__global__ void __launch_bounds__(256) ln_kernel(
    const float* __restrict__ X, const float* __restrict__ gw,
    const float* __restrict__ bw, float* __restrict__ Y)
{
    const int row = blockIdx.x;
    const int t = threadIdx.x;
    float4 v = ((const float4*)(X + (size_t)row * DMODEL))[t];
    float s1 = v.x + v.y + v.z + v.w;
    float s2 = v.x * v.x + v.y * v.y + v.z * v.z + v.w * v.w;
#pragma unroll
    for (int o = 16; o; o >>= 1) {
        s1 += __shfl_xor_sync(~0u, s1, o);
        s2 += __shfl_xor_sync(~0u, s2, o);
    }
    __shared__ float r1[8], r2[8];
    const int w = t >> 5, lane = t & 31;
    if (lane == 0) { r1[w] = s1; r2[w] = s2; }
    __syncthreads();
    if (w == 0) {
        s1 = (lane < 8) ? r1[lane] : 0.0f;
        s2 = (lane < 8) ? r2[lane] : 0.0f;
#pragma unroll
        for (int o = 4; o; o >>= 1) {
            s1 += __shfl_xor_sync(~0u, s1, o);
            s2 += __shfl_xor_sync(~0u, s2, o);
        }
        if (lane == 0) { r1[0] = s1; r2[0] = s2; }
    }
    __syncthreads();
    const float mean = r1[0] * (1.0f / DMODEL);
    const float var  = r2[0] * (1.0f / DMODEL) - mean * mean;
    const float rstd = rsqrtf(var + 1e-5f);
    float4 g4 = ((const float4*)gw)[t];
    float4 b4 = ((const float4*)bw)[t];
    float4 o;
    o.x = (v.x - mean) * rstd * g4.x + b4.x;
    o.y = (v.y - mean) * rstd * g4.y + b4.y;
    o.z = (v.z - mean) * rstd * g4.z + b4.z;
    o.w = (v.w - mean) * rstd * g4.w + b4.w;
    ((float4*)(Y + (size_t)row * DMODEL))[t] = o;
}

// ---------------- launch -----------------------------------------------------
extern "C" void kernel_launch(void* const* d_in, const int* in_sizes, int n_in,
                              void* d_out, int out_size)
{
    const float* x    = (const float*)d_in[0];
    const float* xf   = (const float*)d_in[1];
    const float* Wq   = (const float*)d_in[2];
    const float* bq   = (const float*)d_in[3];
    const float* Wk   = (const float*)d_in[4];
    const float* bk   = (const float*)d_in[5];
    const float* Wv   = (const float*)d_in[6];
    const float* bv   = (const float*)d_in[7];
    const float* Wo   = (const float*)d_in[8];
    const float* bo   = (const float*)d_in[9];
    const float* ln_g = (const float*)d_in[10];
    const float* ln_b = (const float*)d_in[11];
    const float* W1   = (const float*)d_in[12];
    const float* b1   = (const float*)d_in[13];
    const float* W2   = (const float*)d_in[14];
    const float* b2   = (const float*)d_in[15];
    float* out = (float*)d_out;

    float *q, *k, *v, *attn, *res, *ln, *hbuf;
    cudaGetSymbolAddress((void**)&q,    g_q);
    cudaGetSymbolAddress((void**)&k,    g_k);
    cudaGetSymbolAddress((void**)&v,    g_v);
    cudaGetSymbolAddress((void**)&attn, g_attn);
    cudaGetSymbolAddress((void**)&res,  g_res);
    cudaGetSymbolAddress((void**)&ln,   g_ln);
    cudaGetSymbolAddress((void**)&hbuf, g_h);

    const size_t attn_smem = (size_t)(2 * 256 * KPAD + 8 * 64 + 8 * 256) * sizeof(float);
    cudaFuncSetAttribute(attn_kernel, cudaFuncAttributeMaxDynamicSharedMemorySize,
                         (int)attn_smem);

    dim3 blk(256);

    // 1) Q = x@Wq + bq
    sgemm_kernel<0, 0><<<dim3(DMODEL / 128, MQ / 128), blk>>>(
        MQ, DMODEL, DMODEL, x, Wq, bq, nullptr, nullptr, q);
    // 2) K = xf@Wk + bk ; 3) V = xf@Wv + bv
    sgemm_kernel<0, 0><<<dim3(DMODEL / 128, MKV / 128), blk>>>(
        MKV, DMODEL, DTEXT, xf, Wk, bk, nullptr, nullptr, k);
    sgemm_kernel<0, 0><<<dim3(DMODEL / 128, MKV / 128), blk>>>(
        MKV, DMODEL, DTEXT, xf, Wv, bv, nullptr, nullptr, v);
    // 4) attention
    attn_kernel<<<BDIM * NHEADS * (TXQ / QPB), blk, attn_smem>>>(q, k, v, attn);
    // 5) out = attn@Wo + bo  (residual base)
    sgemm_kernel<0, 0><<<dim3(DMODEL / 128, MQ / 128), blk>>>(
        MQ, DMODEL, DMODEL, attn, Wo, bo, nullptr, nullptr, res);
    // 6) ln = LayerNorm(out)
    ln_kernel<<<MQ, blk>>>(res, ln_g, ln_b, ln);
    // 7) h = GELU(ln@W1 + b1)
    sgemm_kernel<1, 0><<<dim3(DFF / 128, MQ / 128), blk>>>(
        MQ, DFF, DMODEL, ln, W1, b1, nullptr, nullptr, hbuf);
    // 8) final = h@W2 + b2 + out + x
    sgemm_kernel<0, 2><<<dim3(DMODEL / 128, MQ / 128), blk>>>(
        MQ, DMODEL, DFF, hbuf, W2, b2, res, x, out);
}

// round 2
// speedup vs baseline: 1.0016x; 1.0016x over previous
#include <cuda_runtime.h>
#include <math.h>

#define BDIM   4
#define TXQ    4096
#define TXFK   256
#define DMODEL 1024
#define DTEXT  768
#define NHEADS 16
#define HDIM   64
#define MQ     (BDIM*TXQ)     // 16384
#define MKV    (BDIM*TXFK)    // 1024
#define DFF    4096
#define ATT_SCALE 0.125f      // 64^-0.5

// ---------------- scratch (device globals; no allocation allowed) -------------
__device__ float g_q   [(size_t)MQ  * DMODEL];   // 64 MB
__device__ float g_k   [(size_t)MKV * DMODEL];   // 4 MB
__device__ float g_v   [(size_t)MKV * DMODEL];   // 4 MB
__device__ float g_attn[(size_t)MQ  * DMODEL];   // 64 MB
__device__ float g_res [(size_t)MQ  * DMODEL];   // out = attn@Wo+bo (residual base)
__device__ float g_ln  [(size_t)MQ  * DMODEL];   // LayerNorm(out)
__device__ float g_h   [(size_t)MQ  * DFF];      // GELU(ln@W1+b1), 256 MB

__device__ __forceinline__ float gelu_exact(float v) {
    return 0.5f * v * (1.0f + erff(v * 0.7071067811865476f));
}

// ---------------- generic fp32 SGEMM: C = act(A@W + bias) [+ res1 + res2] ----
// A: [M,K] row-major, W: [K,N] row-major, C: [M,N] row-major.
// BM=BN=128, BK=16, 256 threads, 8x8 per thread. All shapes divisible.
template<int ACT, int NRES>
__global__ void __launch_bounds__(256, 2) sgemm_kernel(
    int M, int N, int K,
    const float* __restrict__ A, const float* __restrict__ W,
    const float* __restrict__ bias,
    const float* __restrict__ res1, const float* __restrict__ res2,
    float* __restrict__ C)
{
    const int BM = 128, BN = 128, BK = 16;
    __shared__ float As[BK][BM];
    __shared__ float Bs[BK][BN];

    const int tid = threadIdx.x;
    const int tx  = tid & 15;        // 0..15 -> col block
    const int ty  = tid >> 4;        // 0..15 -> row block
    const int bx  = blockIdx.x;      // N tile
    const int by  = blockIdx.y;      // M tile

    // A load mapping: 128 rows x 16 cols -> 512 float4; 2 per thread
    const int a_row  = tid >> 2;          // 0..63 (also +64)
    const int a_col4 = (tid & 3) * 4;     // 0,4,8,12
    // W load mapping: 16 rows x 128 cols -> 512 float4; 2 per thread
    const int b_row  = tid >> 5;          // 0..7 (also +8)
    const int b_col4 = (tid & 31) * 4;    // 0..124

    const float* Ab = A + (size_t)by * BM * K;
    const float* Wb = W + (size_t)bx * BN;

    float acc[8][8];
#pragma unroll
    for (int i = 0; i < 8; i++)
#pragma unroll
        for (int j = 0; j < 8; j++) acc[i][j] = 0.0f;

    for (int k0 = 0; k0 < K; k0 += BK) {
        float4 a0 = *(const float4*)(Ab + (size_t)a_row        * K + k0 + a_col4);
        float4 a1 = *(const float4*)(Ab + (size_t)(a_row + 64) * K + k0 + a_col4);
        float4 w0 = *(const float4*)(Wb + (size_t)(k0 + b_row    ) * N + b_col4);
        float4 w1 = *(const float4*)(Wb + (size_t)(k0 + b_row + 8) * N + b_col4);

        As[a_col4 + 0][a_row     ] = a0.x;
        As[a_col4 + 1][a_row     ] = a0.y;
        As[a_col4 + 2][a_row     ] = a0.z;
        As[a_col4 + 3][a_row     ] = a0.w;
        As[a_col4 + 0][a_row + 64] = a1.x;
        As[a_col4 + 1][a_row + 64] = a1.y;
        As[a_col4 + 2][a_row + 64] = a1.z;
        As[a_col4 + 3][a_row + 64] = a1.w;
        *(float4*)&Bs[b_row    ][b_col4] = w0;
        *(float4*)&Bs[b_row + 8][b_col4] = w1;
        __syncthreads();

#pragma unroll
        for (int kk = 0; kk < BK; kk++) {
            float ra[8], rb[8];
            *(float4*)(ra    ) = *(const float4*)&As[kk][ty * 8    ];
            *(float4*)(ra + 4) = *(const float4*)&As[kk][ty * 8 + 4];
            *(float4*)(rb    ) = *(const float4*)&Bs[kk][tx * 8    ];
            *(float4*)(rb + 4) = *(const float4*)&Bs[kk][tx * 8 + 4];
#pragma unroll
            for (int i = 0; i < 8; i++)
#pragma unroll
                for (int j = 0; j < 8; j++)
                    acc[i][j] += ra[i] * rb[j];
        }
        __syncthreads();
    }

    const int row0 = by * BM + ty * 8;
    const int col0 = bx * BN + tx * 8;
#pragma unroll
    for (int i = 0; i < 8; i++) {
        size_t base = (size_t)(row0 + i) * N + col0;
        float4 o[2];
#pragma unroll
        for (int jj = 0; jj < 2; jj++) {
            float vv[4];
#pragma unroll
            for (int j = 0; j < 4; j++) {
                int jc = jj * 4 + j;
                float v = acc[i][jc] + bias[col0 + jc];
                if (ACT == 1) v = gelu_exact(v);
                if (NRES >= 1) v += res1[base + jc];
                if (NRES >= 2) v += res2[base + jc];
                vv[j] = v;
            }
            o[jj] = make_float4(vv[0], vv[1], vv[2], vv[3]);
        }
        *(float4*)(C + base)     = o[0];
        *(float4*)(C + base + 4) = o[1];
    }
}

// ---------------- attention: per (b, h, q-chunk) block ------------------------
// Q: [MQ, DMODEL] (head h occupies cols h*64..), K/V: [MKV, DMODEL].
// Whole 256x64 K and V head-tiles live in padded smem; softmax over all 256 keys.
#define QPB 256
#define KPAD 65

__global__ void __launch_bounds__(256) attn_kernel(
    const float* __restrict__ Q, const float* __restrict__ K,
    const float* __restrict__ V, float* __restrict__ O)
{
    extern __shared__ float sm[];
    float* Ks = sm;                  // 256*65
    float* Vs = Ks + 256 * KPAD;     // 256*65
    float* qs = Vs + 256 * KPAD;     // 8*64
    float* ps = qs + 8 * 64;         // 8*256

    const int nchunk = TXQ / QPB;    // 16
    const int bid   = blockIdx.x;
    const int chunk = bid % nchunk;
    const int h     = (bid / nchunk) % NHEADS;
    const int b     = bid / (nchunk * NHEADS);

    const int tid  = threadIdx.x;
    const int lane = tid & 31;
    const int w    = tid >> 5;

    // load K,V head tiles (256 rows x 64 cols) into padded smem
    for (int i = tid; i < 256 * 16; i += 256) {
        int j  = i >> 4;
        int dq = (i & 15) * 4;
        size_t gbase = (size_t)(b * TXFK + j) * DMODEL + h * HDIM + dq;
        float4 kv = *(const float4*)(K + gbase);
        float4 vv = *(const float4*)(V + gbase);
        Ks[j * KPAD + dq + 0] = kv.x; Ks[j * KPAD + dq + 1] = kv.y;
        Ks[j * KPAD + dq + 2] = kv.z; Ks[j * KPAD + dq + 3] = kv.w;
        Vs[j * KPAD + dq + 0] = vv.x; Vs[j * KPAD + dq + 1] = vv.y;
        Vs[j * KPAD + dq + 2] = vv.z; Vs[j * KPAD + dq + 3] = vv.w;
    }
    __syncthreads();

    for (int qi = 0; qi < 32; qi++) {
        const int qlocal = w * 32 + qi;
        const size_t qrow = (size_t)b * TXQ + (size_t)chunk * QPB + qlocal;
        const float* qp = Q + qrow * DMODEL + h * HDIM;
        qs[w * 64 + lane]      = qp[lane];
        qs[w * 64 + lane + 32] = qp[lane + 32];
        __syncwarp();

        // scores: lane owns keys j = lane + 32*c (conflict-free via KPAD=65)
        float s[8];
#pragma unroll
        for (int c = 0; c < 8; c++) s[c] = 0.0f;
        for (int d = 0; d < 64; d++) {
            float qd = qs[w * 64 + d];
#pragma unroll
            for (int c = 0; c < 8; c++)
                s[c] += qd * Ks[(lane + 32 * c) * KPAD + d];
        }
#pragma unroll
        for (int c = 0; c < 8; c++) s[c] *= ATT_SCALE;

        float mx = s[0];
#pragma unroll
        for (int c = 1; c < 8; c++) mx = fmaxf(mx, s[c]);
#pragma unroll
        for (int o = 16; o; o >>= 1) mx = fmaxf(mx, __shfl_xor_sync(~0u, mx, o));

        float sum = 0.0f;
#pragma unroll
        for (int c = 0; c < 8; c++) { s[c] = __expf(s[c] - mx); sum += s[c]; }
#pragma unroll
        for (int o = 16; o; o >>= 1) sum += __shfl_xor_sync(~0u, sum, o);
        float inv = 1.0f / sum;

#pragma unroll
        for (int c = 0; c < 8; c++) ps[w * 256 + lane + 32 * c] = s[c] * inv;
        __syncwarp();

        // output: lane owns dims d=lane and d=lane+32
        float o0 = 0.0f, o1 = 0.0f;
        for (int j = 0; j < 256; j++) {
            float p = ps[w * 256 + j];
            o0 += p * Vs[j * KPAD + lane];
            o1 += p * Vs[j * KPAD + lane + 32];
        }
        float* op = O + qrow * DMODEL + h * HDIM;
        op[lane]      = o0;
        op[lane + 32] = o1;
        __syncwarp();   // protect qs/ps reuse next iteration
    }
}

// ---------------- LayerNorm over rows of [MQ, 1024] ---------------------------
__global__ void __launch_bounds__(256) ln_kernel(
    const float* __restrict__ X, const float* __restrict__ gw,
    const float* __restrict__ bw, float* __restrict__ Y)
{
    const int row = blockIdx.x;
    const int t = threadIdx.x;
    float4 v = ((const float4*)(X + (size_t)row * DMODEL))[t];
    float s1 = v.x + v.y + v.z + v.w;
    float s2 = v.x * v.x + v.y * v.y + v.z * v.z + v.w * v.w;
#pragma unroll
    for (int o = 16; o; o >>= 1) {
        s1 += __shfl_xor_sync(~0u, s1, o);
        s2 += __shfl_xor_sync(~0u, s2, o);
    }
    __shared__ float r1[8], r2[8];
    const int w = t >> 5, lane = t & 31;
    if (lane == 0) { r1[w] = s1; r2[w] = s2; }
    __syncthreads();
    if (w == 0) {
        s1 = (lane < 8) ? r1[lane] : 0.0f;
        s2 = (lane < 8) ? r2[lane] : 0.0f;
#pragma unroll
        for (int o = 4; o; o >>= 1) {
            s1 += __shfl_xor_sync(~0u, s1, o);
            s2 += __shfl_xor_sync(~0u, s2, o);
        }
        if (lane == 0) { r1[0] = s1; r2[0] = s2; }
    }
    __syncthreads();
    const float mean = r1[0] * (1.0f / DMODEL);
    const float var  = r2[0] * (1.0f / DMODEL) - mean * mean;
    const float rstd = rsqrtf(var + 1e-5f);
    float4 g4 = ((const float4*)gw)[t];
    float4 b4 = ((const float4*)bw)[t];
    float4 o;
    o.x = (v.x - mean) * rstd * g4.x + b4.x;
    o.y = (v.y - mean) * rstd * g4.y + b4.y;
    o.z = (v.z - mean) * rstd * g4.z + b4.z;
    o.w = (v.w - mean) * rstd * g4.w + b4.w;
    ((float4*)(Y + (size_t)row * DMODEL))[t] = o;
}

// ---------------- launch -----------------------------------------------------
extern "C" void kernel_launch(void* const* d_in, const int* in_sizes, int n_in,
                              void* d_out, int out_size)
{
    const float* x    = (const float*)d_in[0];
    const float* xf   = (const float*)d_in[1];
    const float* Wq   = (const float*)d_in[2];
    const float* bq   = (const float*)d_in[3];
    const float* Wk   = (const float*)d_in[4];
    const float* bk   = (const float*)d_in[5];
    const float* Wv   = (const float*)d_in[6];
    const float* bv   = (const float*)d_in[7];
    const float* Wo   = (const float*)d_in[8];
    const float* bo   = (const float*)d_in[9];
    const float* ln_g = (const float*)d_in[10];
    const float* ln_b = (const float*)d_in[11];
    const float* W1   = (const float*)d_in[12];
    const float* b1   = (const float*)d_in[13];
    const float* W2   = (const float*)d_in[14];
    const float* b2   = (const float*)d_in[15];
    float* out = (float*)d_out;

    float *q, *k, *v, *attn, *res, *ln, *hbuf;
    cudaGetSymbolAddress((void**)&q,    g_q);
    cudaGetSymbolAddress((void**)&k,    g_k);
    cudaGetSymbolAddress((void**)&v,    g_v);
    cudaGetSymbolAddress((void**)&attn, g_attn);
    cudaGetSymbolAddress((void**)&res,  g_res);
    cudaGetSymbolAddress((void**)&ln,   g_ln);
    cudaGetSymbolAddress((void**)&hbuf, g_h);

    const size_t attn_smem = (size_t)(2 * 256 * KPAD + 8 * 64 + 8 * 256) * sizeof(float);
    cudaFuncSetAttribute(attn_kernel, cudaFuncAttributeMaxDynamicSharedMemorySize,
                         (int)attn_smem);

    dim3 blk(256);

    // 1) Q = x@Wq + bq
    sgemm_kernel<0, 0><<<dim3(DMODEL / 128, MQ / 128), blk>>>(
        MQ, DMODEL, DMODEL, x, Wq, bq, nullptr, nullptr, q);
    // 2) K = xf@Wk + bk ; 3) V = xf@Wv + bv
    sgemm_kernel<0, 0><<<dim3(DMODEL / 128, MKV / 128), blk>>>(
        MKV, DMODEL, DTEXT, xf, Wk, bk, nullptr, nullptr, k);
    sgemm_kernel<0, 0><<<dim3(DMODEL / 128, MKV / 128), blk>>>(
        MKV, DMODEL, DTEXT, xf, Wv, bv, nullptr, nullptr, v);
    // 4) attention
    attn_kernel<<<BDIM * NHEADS * (TXQ / QPB), blk, attn_smem>>>(q, k, v, attn);
    // 5) out = attn@Wo + bo  (residual base)
    sgemm_kernel<0, 0><<<dim3(DMODEL / 128, MQ / 128), blk>>>(
        MQ, DMODEL, DMODEL, attn, Wo, bo, nullptr, nullptr, res);
    // 6) ln = LayerNorm(out)
    ln_kernel<<<MQ, blk>>>(res, ln_g, ln_b, ln);
    // 7) h = GELU(ln@W1 + b1)
    sgemm_kernel<1, 0><<<dim3(DFF / 128, MQ / 128), blk>>>(
        MQ, DFF, DMODEL, ln, W1, b1, nullptr, nullptr, hbuf);
    // 8) final = h@W2 + b2 + out + x
    sgemm_kernel<0, 2><<<dim3(DMODEL / 128, MQ / 128), blk>>>(
        MQ, DMODEL, DFF, hbuf, W2, b2, res, x, out);
}